// round 1
// baseline (speedup 1.0000x reference)
#include <cuda_runtime.h>

// Wilson-Cowan population dynamics, N=1048576 elements, `steps` (=100) serial
// ODE steps per element. Compute-bound: 4 MUFU (2x EX2 + 2x RCP) + ~10 fma-pipe
// ops per element-step. All gains/thresholds/log2e scaling folded into
// per-element constants so each sigmoid is exactly EX2 -> FADD -> RCP.

#define TAU_E  10.0f
#define TAU_I  5.0f
#define W_EE   12.0f
#define W_EI   4.0f
#define W_IE   13.0f
#define W_II   11.0f
#define THRESH 4.0f
#define DT     0.1f
#define LOG2E  1.4426950408889634f

__device__ __forceinline__ float ex2f(float x) {
    float r;
    asm("ex2.approx.f32 %0, %1;" : "=f"(r) : "f"(x));
    return r;
}
__device__ __forceinline__ float rcpf(float x) {
    float r;
    asm("rcp.approx.f32 %0, %1;" : "=f"(r) : "f"(x));
    return r;
}

__global__ __launch_bounds__(256)
void wilson_cowan_kernel(const float4* __restrict__ E0,
                         const float4* __restrict__ I0,
                         const float4* __restrict__ IextE,
                         const float4* __restrict__ IextI,
                         const int*    __restrict__ steps_ptr,
                         float* __restrict__ out,
                         int n,          // total elements (N)
                         int n4,         // N/4
                         int out_size)
{
    int i = blockIdx.x * blockDim.x + threadIdx.x;

    // zero any trailing outputs (oscillation_power scalar, etc.)
    if (blockIdx.x == 0 && threadIdx.x == 0) {
        for (int k = 2 * n; k < out_size; ++k) out[k] = 0.0f;
    }
    if (i >= n4) return;

    const int steps = steps_ptr ? __ldg(steps_ptr) : 100;

    float4 e4 = E0[i];
    float4 i4 = I0[i];
    float4 xe4 = IextE[i];
    float4 xi4 = IextI[i];

    float E[4] = {e4.x, e4.y, e4.z, e4.w};
    float I[4] = {i4.x, i4.y, i4.z, i4.w};
    // y = -L * (input - THRESH) so that ex2(y) = exp(-(input - THRESH))
    // y_E = (-L*W_EE)*E + (L*W_EI)*I + L*(THRESH - IextE)
    float cE[4], cI[4];
    {
        const float* xe = &xe4.x;
        const float* xi = &xi4.x;
        #pragma unroll
        for (int j = 0; j < 4; ++j) {
            cE[j] = (THRESH - xe[j]) * LOG2E;
            cI[j] = (THRESH - xi[j]) * LOG2E;
        }
    }

    const float A_EE = -W_EE * LOG2E;   // -12L
    const float A_EI =  W_EI * LOG2E;   // +4L  (note: -(-W_EI))
    const float A_IE = -W_IE * LOG2E;   // -13L
    const float A_II =  W_II * LOG2E;   // +11L
    const float KE = DT / TAU_E;        // 0.01
    const float KI = DT / TAU_I;        // 0.02

    #pragma unroll 4
    for (int s = 0; s < steps; ++s) {
        #pragma unroll
        for (int j = 0; j < 4; ++j) {
            float yE = fmaf(A_EE, E[j], fmaf(A_EI, I[j], cE[j]));
            float yI = fmaf(A_IE, E[j], fmaf(A_II, I[j], cI[j]));
            float sE = rcpf(1.0f + ex2f(yE));   // sigmoid(input_E - 4)
            float sI = rcpf(1.0f + ex2f(yI));
            E[j] = __saturatef(fmaf(KE, sE - E[j], E[j]));
            I[j] = __saturatef(fmaf(KI, sI - I[j], I[j]));
        }
    }

    float4 eo = make_float4(E[0], E[1], E[2], E[3]);
    float4 io = make_float4(I[0], I[1], I[2], I[3]);
    reinterpret_cast<float4*>(out)[i]      = eo;
    reinterpret_cast<float4*>(out + n)[i]  = io;
}

extern "C" void kernel_launch(void* const* d_in, const int* in_sizes, int n_in,
                              void* d_out, int out_size)
{
    const float4* E0 = (const float4*)d_in[0];
    const float4* I0 = (const float4*)d_in[1];
    const float4* IextE = (const float4*)d_in[2];
    const float4* IextI = (const float4*)d_in[3];
    const int* steps_ptr = (n_in >= 5) ? (const int*)d_in[4] : nullptr;

    int n = in_sizes[0];
    int n4 = n / 4;
    int threads = 256;
    int blocks = (n4 + threads - 1) / threads;

    wilson_cowan_kernel<<<blocks, threads>>>(E0, I0, IextE, IextI, steps_ptr,
                                             (float*)d_out, n, n4, out_size);
}

// round 2
// speedup vs baseline: 1.7457x; 1.7457x over previous
#include <cuda_runtime.h>

// Wilson-Cowan, N=2^20 elements, 100 serial steps.
// R2: sigmoid via MUFU.TANH (1 MUFU vs EX2+RCP's 2) -> halves the MUFU floor.
//     All scalar FMAs packed as fma.rn.f32x2 (FFMA2) over element pairs so the
//     fma pipe sits at ~50% while MUFU binds at ~47us.
//
// Folding:
//   sigmoid(g*(x-th)) = 0.5 + 0.5*tanh(0.5*(x-th))        (g = 1)
//   yE = 6E - 2I + 0.5*(IextE - 4)
//   yI = 6.5E - 5.5I + 0.5*(IextI - 4)
//   E' = (1-kE)E + 0.5kE + 0.5kE*tanh(yE),  kE = dt/tauE = 0.01
//   I' = (1-kI)I + 0.5kI + 0.5kI*tanh(yI),  kI = dt/tauI = 0.02
// Update is a convex combination of E and sigma in (0,1) -> [0,1] invariant
// to ~1 ulp; clip applied once (scalar, exact) at the end.

typedef unsigned long long u64;

__device__ __forceinline__ u64 pack2(float lo, float hi) {
    u64 r;
    asm("mov.b64 %0, {%1, %2};" : "=l"(r) : "f"(lo), "f"(hi));
    return r;
}
__device__ __forceinline__ void unpack2(float& lo, float& hi, u64 v) {
    asm("mov.b64 {%0, %1}, %2;" : "=f"(lo), "=f"(hi) : "l"(v));
}
__device__ __forceinline__ u64 fma2(u64 a, u64 b, u64 c) {
    u64 d;
    asm("fma.rn.f32x2 %0, %1, %2, %3;" : "=l"(d) : "l"(a), "l"(b), "l"(c));
    return d;
}
__device__ __forceinline__ float tanhf_approx(float x) {
    float r;
    asm("tanh.approx.f32 %0, %1;" : "=f"(r) : "f"(x));
    return r;
}

__global__ __launch_bounds__(256)
void wilson_cowan_kernel(const float4* __restrict__ E0,
                         const float4* __restrict__ I0,
                         const float4* __restrict__ IextE,
                         const float4* __restrict__ IextI,
                         const int*    __restrict__ steps_ptr,
                         float* __restrict__ out,
                         int n,          // total elements (N)
                         int n4,         // N/4
                         int out_size)
{
    int i = blockIdx.x * blockDim.x + threadIdx.x;

    if (blockIdx.x == 0 && threadIdx.x == 0) {
        for (int k = 2 * n; k < out_size; ++k) out[k] = 0.0f;
    }
    if (i >= n4) return;

    const int steps = steps_ptr ? __ldg(steps_ptr) : 100;

    float4 e4  = E0[i];
    float4 i4  = I0[i];
    float4 xe4 = IextE[i];
    float4 xi4 = IextI[i];

    // two packed pairs per thread: (x,y) and (z,w)
    u64 E2[2] = { pack2(e4.x, e4.y), pack2(e4.z, e4.w) };
    u64 I2[2] = { pack2(i4.x, i4.y), pack2(i4.z, i4.w) };
    u64 cE2[2] = { pack2(0.5f * (xe4.x - 4.0f), 0.5f * (xe4.y - 4.0f)),
                   pack2(0.5f * (xe4.z - 4.0f), 0.5f * (xe4.w - 4.0f)) };
    u64 cI2[2] = { pack2(0.5f * (xi4.x - 4.0f), 0.5f * (xi4.y - 4.0f)),
                   pack2(0.5f * (xi4.z - 4.0f), 0.5f * (xi4.w - 4.0f)) };

    const u64 AEE = pack2( 6.0f,  6.0f);   // 0.5 * 12
    const u64 AEI = pack2(-2.0f, -2.0f);   // 0.5 * -4
    const u64 AIE = pack2( 6.5f,  6.5f);   // 0.5 * 13
    const u64 AII = pack2(-5.5f, -5.5f);   // 0.5 * -11
    const u64 ME  = pack2(0.99f, 0.99f);   // 1 - kE
    const u64 BE  = pack2(0.005f, 0.005f); // 0.5 * kE (both the affine and tanh coeff)
    const u64 MI  = pack2(0.98f, 0.98f);   // 1 - kI
    const u64 BI  = pack2(0.01f, 0.01f);   // 0.5 * kI

    #pragma unroll 2
    for (int s = 0; s < steps; ++s) {
        #pragma unroll
        for (int p = 0; p < 2; ++p) {
            u64 yE = fma2(AEE, E2[p], fma2(AEI, I2[p], cE2[p]));
            u64 yI = fma2(AIE, E2[p], fma2(AII, I2[p], cI2[p]));
            float a, b;
            unpack2(a, b, yE);
            u64 tE = pack2(tanhf_approx(a), tanhf_approx(b));
            unpack2(a, b, yI);
            u64 tI = pack2(tanhf_approx(a), tanhf_approx(b));
            E2[p] = fma2(BE, tE, fma2(ME, E2[p], BE));
            I2[p] = fma2(BI, tI, fma2(MI, I2[p], BI));
        }
    }

    float4 eo, io;
    unpack2(eo.x, eo.y, E2[0]); unpack2(eo.z, eo.w, E2[1]);
    unpack2(io.x, io.y, I2[0]); unpack2(io.z, io.w, I2[1]);
    // exact clip to match reference (in-loop it is inactive to ~1 ulp)
    eo.x = __saturatef(eo.x); eo.y = __saturatef(eo.y);
    eo.z = __saturatef(eo.z); eo.w = __saturatef(eo.w);
    io.x = __saturatef(io.x); io.y = __saturatef(io.y);
    io.z = __saturatef(io.z); io.w = __saturatef(io.w);

    reinterpret_cast<float4*>(out)[i]     = eo;
    reinterpret_cast<float4*>(out + n)[i] = io;
}

extern "C" void kernel_launch(void* const* d_in, const int* in_sizes, int n_in,
                              void* d_out, int out_size)
{
    const float4* E0    = (const float4*)d_in[0];
    const float4* I0    = (const float4*)d_in[1];
    const float4* IextE = (const float4*)d_in[2];
    const float4* IextI = (const float4*)d_in[3];
    const int* steps_ptr = (n_in >= 5) ? (const int*)d_in[4] : nullptr;

    int n = in_sizes[0];
    int n4 = n / 4;
    int threads = 256;
    int blocks = (n4 + threads - 1) / threads;

    wilson_cowan_kernel<<<blocks, threads>>>(E0, I0, IextE, IextI, steps_ptr,
                                             (float*)d_out, n, n4, out_size);
}